// round 4
// baseline (speedup 1.0000x reference)
#include <cuda_runtime.h>
#include <cuda_fp16.h>

// HybridEulerIntegrator: a_{t+1} = a_t + C * (MLP([x_t, a_t]))^3
// MLP: 2 -> 64 (tanh) -> 1, hidden layer in packed f16x2.
// Layout: TPE=2 threads per element, 32 hidden units (16 half2 pairs) per thread.
// One shfl per step; recurrence state in f32.
// x [2048, 16384], a0 [16384], W1 [2,64], b1 [64], W2 [64,1], b2 [1]

#define T_STEPS 2048
#define BATCH   16384
#define HIDDEN  64
#define TPE     2
#define PAIRS   16   // half2 pairs per thread (32 hidden units)
#define BLOCK   256
#define W2SCALE 0.125f

__device__ __forceinline__ __half2 tanh_h2(__half2 v) {
    unsigned r, in = *(unsigned*)&v;
    asm("tanh.approx.f16x2 %0, %1;" : "=r"(r) : "r"(in));
    return *(__half2*)&r;
}

__global__ void __launch_bounds__(BLOCK, 1)
hybrid_euler_kernel(const float* __restrict__ x,
                    const float* __restrict__ a0,
                    const float* __restrict__ W1,
                    const float* __restrict__ b1,
                    const float* __restrict__ W2,
                    const float* __restrict__ b2,
                    float* __restrict__ out)
{
    const int tid = blockIdx.x * BLOCK + threadIdx.x;
    const int e   = tid >> 1;        // element index
    const int s   = tid & 1;         // half (0: units 0..31, 1: units 32..63)

    // This thread's 32 hidden units as 16 half2 pairs, all in registers.
    __half2 w1x[PAIRS], w1a[PAIRS], b1h[PAIRS], w2h[PAIRS];
#pragma unroll
    for (int p = 0; p < PAIRS; p++) {
        const int j = s * (2 * PAIRS) + 2 * p;
        w1x[p] = __floats2half2_rn(W1[j],           W1[j + 1]);
        w1a[p] = __floats2half2_rn(W1[HIDDEN + j],  W1[HIDDEN + j + 1]);
        b1h[p] = __floats2half2_rn(b1[j],           b1[j + 1]);
        w2h[p] = __floats2half2_rn(W2[j] * W2SCALE, W2[j + 1] * W2SCALE);
    }
    const float bias2 = b2[0];

    float a = a0[e];
    const float* xp = x + e;
    float*       op = out + e;

    // Software-pipeline the x stream (independent of the a-chain).
    float xt = __ldg(xp);

    for (int t = 0; t < T_STEPS; t++) {
        float xt_next = 0.0f;
        if (t + 1 < T_STEPS) xt_next = __ldg(xp + BATCH);
        xp += BATCH;

        const __half2 xh = __float2half2_rn(xt);
        const __half2 ah = __float2half2_rn(a);

        // Four independent f16x2 accumulator chains, each 4 deep.
        __half2 acc0 = __float2half2_rn(0.0f);
        __half2 acc1 = acc0, acc2 = acc0, acc3 = acc0;
#pragma unroll
        for (int p = 0; p < PAIRS; p += 4) {
            __half2 pre0 = __hfma2(xh, w1x[p],     __hfma2(ah, w1a[p],     b1h[p]));
            __half2 pre1 = __hfma2(xh, w1x[p + 1], __hfma2(ah, w1a[p + 1], b1h[p + 1]));
            __half2 pre2 = __hfma2(xh, w1x[p + 2], __hfma2(ah, w1a[p + 2], b1h[p + 2]));
            __half2 pre3 = __hfma2(xh, w1x[p + 3], __hfma2(ah, w1a[p + 3], b1h[p + 3]));
            acc0 = __hfma2(tanh_h2(pre0), w2h[p],     acc0);
            acc1 = __hfma2(tanh_h2(pre1), w2h[p + 1], acc1);
            acc2 = __hfma2(tanh_h2(pre2), w2h[p + 2], acc2);
            acc3 = __hfma2(tanh_h2(pre3), w2h[p + 3], acc3);
        }
        const __half2 accs = __hadd2(__hadd2(acc0, acc1), __hadd2(acc2, acc3));
        const float2 f2 = __half22float2(accs);
        float dk = f2.x + f2.y;

        // Combine the two threads of this element (single shfl).
        dk += __shfl_xor_sync(0xFFFFFFFFu, dk, 1);
        dk = fmaf(dk, 8.0f, bias2);   // undo W2SCALE, add output bias

        // a += C * dk^3
        const float dk2 = dk * dk;
        a = fmaf(0.001f * dk, dk2, a);

        if (s == 0) *op = a;
        op += BATCH;

        xt = xt_next;
    }
}

extern "C" void kernel_launch(void* const* d_in, const int* in_sizes, int n_in,
                              void* d_out, int out_size)
{
    const float* x  = (const float*)d_in[0];
    const float* a0 = (const float*)d_in[1];
    const float* W1 = (const float*)d_in[2];
    const float* b1 = (const float*)d_in[3];
    const float* W2 = (const float*)d_in[4];
    const float* b2 = (const float*)d_in[5];
    float* out = (float*)d_out;

    const int total_threads = BATCH * TPE;           // 32768
    const int grid = total_threads / BLOCK;          // 128 blocks (<=1 per SM)
    hybrid_euler_kernel<<<grid, BLOCK>>>(x, a0, W1, b1, W2, b2, out);
}

// round 5
// speedup vs baseline: 1.3034x; 1.3034x over previous
#include <cuda_runtime.h>
#include <cuda_fp16.h>

// HybridEulerIntegrator: a_{t+1} = a_t + C * (MLP([x_t, a_t]))^3
// MLP: 2 -> 64 (tanh) -> 1, hidden layer in packed f16x2, f32 recurrence state.
// TPE=8 lanes per element, BLOCK=64 for even SM load balance (2048 blocks -> 14/13 per SM).
// x-part of pre-activation precomputed one step ahead (off the a-dependency chain).

#define T_STEPS 2048
#define BATCH   16384
#define HIDDEN  64
#define TPE     8
#define PAIRS   4    // half2 pairs per thread (8 hidden units)
#define BLOCK   64
#define W2SCALE 0.125f

__device__ __forceinline__ __half2 tanh_h2(__half2 v) {
    unsigned r, in = *(unsigned*)&v;
    asm("tanh.approx.f16x2 %0, %1;" : "=r"(r) : "r"(in));
    return *(__half2*)&r;
}

__global__ void __launch_bounds__(BLOCK)
hybrid_euler_kernel(const float* __restrict__ x,
                    const float* __restrict__ a0,
                    const float* __restrict__ W1,
                    const float* __restrict__ b1,
                    const float* __restrict__ W2,
                    const float* __restrict__ b2,
                    float* __restrict__ out)
{
    const int tid = blockIdx.x * BLOCK + threadIdx.x;
    const int e   = tid >> 3;        // element index
    const int s   = tid & 7;         // sub-lane within 8-lane group

    // This thread's 8 hidden units as 4 half2 pairs (loop-invariant, registers).
    __half2 w1x[PAIRS], w1a[PAIRS], b1h[PAIRS], w2h[PAIRS];
#pragma unroll
    for (int p = 0; p < PAIRS; p++) {
        const int j = s * (2 * PAIRS) + 2 * p;
        w1x[p] = __floats2half2_rn(W1[j],           W1[j + 1]);
        w1a[p] = __floats2half2_rn(W1[HIDDEN + j],  W1[HIDDEN + j + 1]);
        b1h[p] = __floats2half2_rn(b1[j],           b1[j + 1]);
        w2h[p] = __floats2half2_rn(W2[j] * W2SCALE, W2[j + 1] * W2SCALE);
    }
    const float bias2 = b2[0];

    float a = a0[e];
    const float* xp = x + e;
    float*       op = out + e;

    // Prologue: load x_0 and precompute its contribution to the pre-activations.
    // xpart[p] = x_t * w1x[p] + b1[p]  (independent of a -> off the critical chain)
    __half2 xpart[PAIRS];
    {
        const __half2 xh0 = __float2half2_rn(__ldg(xp));
#pragma unroll
        for (int p = 0; p < PAIRS; p++)
            xpart[p] = __hfma2(xh0, w1x[p], b1h[p]);
    }

    for (int t = 0; t < T_STEPS; t++) {
        // Pipelined load of x_{t+1} (never on the a-chain).
        float xt_next = 0.0f;
        if (t + 1 < T_STEPS) xt_next = __ldg(xp + BATCH);
        xp += BATCH;

        const __half2 ah = __float2half2_rn(a);

        // Critical chain: ah -> 1 HFMA2 -> tanh -> acc.
        __half2 acc0 = __float2half2_rn(0.0f);
        __half2 acc1 = acc0;
#pragma unroll
        for (int p = 0; p < PAIRS; p += 2) {
            __half2 pre0 = __hfma2(ah, w1a[p],     xpart[p]);
            __half2 pre1 = __hfma2(ah, w1a[p + 1], xpart[p + 1]);
            acc0 = __hfma2(tanh_h2(pre0), w2h[p],     acc0);
            acc1 = __hfma2(tanh_h2(pre1), w2h[p + 1], acc1);
        }

        // Off-chain: prepare next step's x-part while the reduction chain drains.
        const __half2 xhn = __float2half2_rn(xt_next);
#pragma unroll
        for (int p = 0; p < PAIRS; p++)
            xpart[p] = __hfma2(xhn, w1x[p], b1h[p]);

        const __half2 accs = __hadd2(acc0, acc1);
        const float2 f2 = __half22float2(accs);
        float dk = f2.x + f2.y;

        // Reduce across the 8 lanes of this element's group.
        dk += __shfl_xor_sync(0xFFFFFFFFu, dk, 1);
        dk += __shfl_xor_sync(0xFFFFFFFFu, dk, 2);
        dk += __shfl_xor_sync(0xFFFFFFFFu, dk, 4);
        dk = fmaf(dk, 8.0f, bias2);   // undo W2SCALE, add output bias

        // a += C * dk^3
        const float dk2 = dk * dk;
        a = fmaf(0.001f * dk, dk2, a);

        if (s == 0) *op = a;
        op += BATCH;
    }
}

extern "C" void kernel_launch(void* const* d_in, const int* in_sizes, int n_in,
                              void* d_out, int out_size)
{
    const float* x  = (const float*)d_in[0];
    const float* a0 = (const float*)d_in[1];
    const float* W1 = (const float*)d_in[2];
    const float* b1 = (const float*)d_in[3];
    const float* W2 = (const float*)d_in[4];
    const float* b2 = (const float*)d_in[5];
    float* out = (float*)d_out;

    const int total_threads = BATCH * TPE;           // 131072
    const int grid = total_threads / BLOCK;          // 2048 blocks of 2 warps
    hybrid_euler_kernel<<<grid, BLOCK>>>(x, a0, W1, b1, W2, b2, out);
}